// round 2
// baseline (speedup 1.0000x reference)
#include <cuda_runtime.h>
#include <math.h>

// Problem constants
#define Bq 16
#define Tq 750
#define Fq 4096
#define Cq 20
#define Kq 93           // T / 8
#define F4 (Fq/4)       // 1024 x 16B per row
#define NROWS (Bq*Tq)   // 12000

// Output layout (concatenated in reference return order, float32)
#define OFF_SA   0L
#define OFF_SB   320L
#define OFF_FA   640L
#define OFF_FB   (OFF_FA + (long)Bq*Kq*Fq)
#define OFF_FEAT (OFF_FB + (long)Bq*Kq*Fq)
#define OFF_CS   (OFF_FEAT + (long)NROWS*Fq)

// Scratch (static device globals; no runtime allocation)
__device__ float g_cas[NROWS*Cq];
__device__ float g_mag[NROWS];
__device__ int   g_idx_act[Bq*Kq];
__device__ int   g_idx_bkg[Bq*Kq];
__device__ float g_sa[Bq*Cq];
__device__ float g_sb[Bq*Cq];

// ---------------------------------------------------------------------------
// Packed f32x2 helpers (Blackwell FFMA2 — only reachable via PTX)
// ---------------------------------------------------------------------------
__device__ __forceinline__ unsigned long long fma2(unsigned long long a,
                                                   unsigned long long b,
                                                   unsigned long long c)
{
    unsigned long long d;
    asm("fma.rn.f32x2 %0, %1, %2, %3;" : "=l"(d) : "l"(a), "l"(b), "l"(c));
    return d;
}
__device__ __forceinline__ unsigned long long mul2(unsigned long long a,
                                                   unsigned long long b)
{
    unsigned long long d;
    asm("mul.rn.f32x2 %0, %1, %2;" : "=l"(d) : "l"(a), "l"(b));
    return d;
}
__device__ __forceinline__ float pairsum(unsigned long long v)
{
    float lo, hi;
    asm("mov.b64 {%0,%1}, %2;" : "=f"(lo), "=f"(hi) : "l"(v));
    return lo + hi;
}

// Monotone float <-> uint order map (total order, works for any sign)
__device__ __forceinline__ unsigned int fmap(float f)
{
    unsigned int u = __float_as_uint(f);
    return (u & 0x80000000u) ? ~u : (u | 0x80000000u);
}
__device__ __forceinline__ float funmap(unsigned int u)
{
    return (u & 0x80000000u) ? __uint_as_float(u ^ 0x80000000u)
                             : __uint_as_float(~u);
}

// Block-wide k-th largest (1-based k) over mapped uints in smem.
// 32-step bitwise radix descent; all threads return the same value.
__device__ unsigned int kth_largest(const unsigned int* __restrict__ v, int n,
                                    int k, int* s_cnt, int tid, int nthr)
{
    unsigned int prefix = 0, mask = 0;
    for (int bit = 31; bit >= 0; --bit) {
        if (tid == 0) *s_cnt = 0;
        __syncthreads();
        const unsigned int m2   = mask | (1u << bit);
        const unsigned int test = prefix | (1u << bit);
        int c = 0;
        for (int t = tid; t < n; t += nthr)
            c += ((v[t] & m2) == test);
        if (c) atomicAdd(s_cnt, c);
        __syncthreads();
        const int cnt = *s_cnt;
        if (cnt >= k) prefix = test; else k -= cnt;
        mask = m2;
        __syncthreads();
    }
    return prefix;
}

// ---------------------------------------------------------------------------
// K1: fused stream kernel. Each warp owns 2 rows (b,t):
//   masked GEMM (20 classes, packed f32x2 accumulators), sumsq, features copy,
//   per-row softmax -> cas_softmax; raw cas + mag -> scratch.
// ---------------------------------------------------------------------------
__global__ __launch_bounds__(256) void k_main(const ulonglong2* __restrict__ x2,
                                              const ulonglong2* __restrict__ m2,
                                              const ulonglong2* __restrict__ w2,
                                              float* __restrict__ out)
{
    const int warp = (blockIdx.x * blockDim.x + threadIdx.x) >> 5;
    const int lane = threadIdx.x & 31;
    const int r0 = warp * 2;
    const int r1 = r0 + 1;
    if (r1 >= NROWS) return;

    const ulonglong2* __restrict__ xa = x2 + (long)r0 * F4;
    const ulonglong2* __restrict__ xb = x2 + (long)r1 * F4;
    const ulonglong2* __restrict__ ma = m2 + (long)r0 * F4;
    const ulonglong2* __restrict__ mb = m2 + (long)r1 * F4;
    ulonglong2* __restrict__ fo0 = reinterpret_cast<ulonglong2*>(out + OFF_FEAT) + (long)r0 * F4;
    ulonglong2* __restrict__ fo1 = reinterpret_cast<ulonglong2*>(out + OFF_FEAT) + (long)r1 * F4;

    unsigned long long acc0[Cq], acc1[Cq];
#pragma unroll
    for (int c = 0; c < Cq; c++) { acc0[c] = 0ull; acc1[c] = 0ull; }
    unsigned long long sq0 = 0ull, sq1 = 0ull;

    for (int i = 0; i < F4 / 32; i++) {
        const int j = lane + 32 * i;
        ulonglong2 a  = xa[j];
        ulonglong2 am = ma[j];
        ulonglong2 b  = xb[j];
        ulonglong2 bm = mb[j];
        fo0[j] = a;
        fo1[j] = b;
        unsigned long long paxy = mul2(a.x, am.x);
        unsigned long long pazw = mul2(a.y, am.y);
        unsigned long long pbxy = mul2(b.x, bm.x);
        unsigned long long pbzw = mul2(b.y, bm.y);
        sq0 = fma2(a.x, a.x, sq0);
        sq0 = fma2(a.y, a.y, sq0);
        sq1 = fma2(b.x, b.x, sq1);
        sq1 = fma2(b.y, b.y, sq1);
#pragma unroll
        for (int c = 0; c < Cq; c++) {
            ulonglong2 w = w2[c * F4 + j];
            acc0[c] = fma2(paxy, w.x, acc0[c]);
            acc0[c] = fma2(pazw, w.y, acc0[c]);
            acc1[c] = fma2(pbxy, w.x, acc1[c]);
            acc1[c] = fma2(pbzw, w.y, acc1[c]);
        }
    }

    float fa0[Cq], fa1[Cq];
#pragma unroll
    for (int c = 0; c < Cq; c++) { fa0[c] = pairsum(acc0[c]); fa1[c] = pairsum(acc1[c]); }
    float fsq0 = pairsum(sq0), fsq1 = pairsum(sq1);

    // warp tree reduction (butterfly)
#pragma unroll
    for (int off = 16; off > 0; off >>= 1) {
        fsq0 += __shfl_xor_sync(0xffffffffu, fsq0, off);
        fsq1 += __shfl_xor_sync(0xffffffffu, fsq1, off);
#pragma unroll
        for (int c = 0; c < Cq; c++) {
            fa0[c] += __shfl_xor_sync(0xffffffffu, fa0[c], off);
            fa1[c] += __shfl_xor_sync(0xffffffffu, fa1[c], off);
        }
    }

    float v0 = 0.f, v1 = 0.f;
#pragma unroll
    for (int c = 0; c < Cq; c++) {
        if (lane == c) { v0 = fa0[c]; v1 = fa1[c]; }
    }

    // softmax over C=20 across lanes
    float mm0 = (lane < Cq) ? v0 : -INFINITY;
    float mm1 = (lane < Cq) ? v1 : -INFINITY;
#pragma unroll
    for (int off = 16; off > 0; off >>= 1) {
        mm0 = fmaxf(mm0, __shfl_xor_sync(0xffffffffu, mm0, off));
        mm1 = fmaxf(mm1, __shfl_xor_sync(0xffffffffu, mm1, off));
    }
    float e0 = (lane < Cq) ? expf(v0 - mm0) : 0.f;
    float e1 = (lane < Cq) ? expf(v1 - mm1) : 0.f;
    float s0 = e0, s1 = e1;
#pragma unroll
    for (int off = 16; off > 0; off >>= 1) {
        s0 += __shfl_xor_sync(0xffffffffu, s0, off);
        s1 += __shfl_xor_sync(0xffffffffu, s1, off);
    }
    if (lane < Cq) {
        out[OFF_CS + (long)r0 * Cq + lane] = e0 / s0;
        out[OFF_CS + (long)r1 * Cq + lane] = e1 / s1;
        g_cas[r0 * Cq + lane] = v0;
        g_cas[r1 * Cq + lane] = v1;
    }
    if (lane == 0) {
        g_mag[r0] = sqrtf(fsq0);
        g_mag[r1] = sqrtf(fsq1);
    }
}

// ---------------------------------------------------------------------------
// K2: per-batch selection. Radix-select the 93rd-largest threshold, then
// stable rank-count ONLY the ~93 candidates (exact jax.lax.top_k order).
// ---------------------------------------------------------------------------
__global__ __launch_bounds__(256) void k_select(const float* __restrict__ sel)
{
    const int b = blockIdx.x;
    const int tid = threadIdx.x;
    __shared__ unsigned int ua[Tq];
    __shared__ unsigned int ub[Tq];
    __shared__ float red[256];
    __shared__ int s_cnt;

    // load mags, block max
    float lmax = -INFINITY;
    for (int t = tid; t < Tq; t += 256) {
        float m = g_mag[b * Tq + t];
        ua[t] = __float_as_uint(m);   // stash raw mag bits temporarily (mag >= 0)
        lmax = fmaxf(lmax, m);
    }
    red[tid] = lmax;
    __syncthreads();
    for (int s = 128; s > 0; s >>= 1) {
        if (tid < s) red[tid] = fmaxf(red[tid], red[tid + s]);
        __syncthreads();
    }
    const float mx = red[0];
    __syncthreads();

    for (int t = tid; t < Tq; t += 256) {
        float m = __uint_as_float(ua[t]);
        float s = sel[b * Tq + t];
        float va = m * s + 0.0f;           // flush -0 -> +0
        float vr = (mx - m) * s + 0.0f;
        ua[t] = fmap(va);
        ub[t] = fmap(vr);
    }
    __syncthreads();

    const unsigned int thA = kth_largest(ua, Tq, Kq, &s_cnt, tid, 256);
    const unsigned int thB = kth_largest(ub, Tq, Kq, &s_cnt, tid, 256);

    for (int t = tid; t < Tq; t += 256) {
        unsigned int xA = ua[t];
        unsigned int xB = ub[t];
        if (xA >= thA) {
            int r = 0;
            for (int j = 0; j < Tq; j++) {
                unsigned int u = ua[j];
                r += (u > xA) || (u == xA && j < t);
            }
            if (r < Kq) g_idx_act[b * Kq + r] = t;
        }
        if (xB >= thB) {
            int r = 0;
            for (int j = 0; j < Tq; j++) {
                unsigned int u = ub[j];
                r += (u > xB) || (u == xB && j < t);
            }
            if (r < Kq) g_idx_bkg[b * Kq + r] = t;
        }
    }
}

// ---------------------------------------------------------------------------
// K3: gather feat_act / feat_bkg rows from x.
// ---------------------------------------------------------------------------
__global__ __launch_bounds__(128) void k_gather(const float4* __restrict__ x4,
                                                float* __restrict__ out)
{
    const int i = blockIdx.x;           // b*93 + k
    const int b = i / Kq;
    const int t = (blockIdx.y == 0) ? g_idx_act[i] : g_idx_bkg[i];
    const float4* __restrict__ src = x4 + ((long)(b * Tq + t)) * F4;
    float4* __restrict__ dst =
        reinterpret_cast<float4*>(out + (blockIdx.y == 0 ? OFF_FA : OFF_FB)) + (long)i * F4;
#pragma unroll
    for (int j = threadIdx.x; j < F4; j += 128) dst[j] = src[j];
}

// ---------------------------------------------------------------------------
// K4: per-(b,c): sum of top-93 cas over T via threshold (order-independent),
// plus mean of cas at idx_bkg.
// ---------------------------------------------------------------------------
__global__ __launch_bounds__(256) void k_scores()
{
    const int bc = blockIdx.x;          // b*20 + c
    const int b = bc / Cq;
    const int c = bc % Cq;
    const int tid = threadIdx.x;
    __shared__ float col[Tq];
    __shared__ unsigned int uv[Tq];
    __shared__ float redA[256];
    __shared__ float redB[256];
    __shared__ float redC[256];
    __shared__ int s_cnt;

    for (int t = tid; t < Tq; t += 256) {
        float v = g_cas[(b * Tq + t) * Cq + c];
        col[t] = v;
        uv[t] = fmap(v);
    }
    __syncthreads();

    const unsigned int th = kth_largest(uv, Tq, Kq, &s_cnt, tid, 256);
    const float thf = funmap(th);

    float sgt = 0.f;   // sum of strictly-greater-than-threshold values
    float cgt = 0.f;   // count of them
    for (int t = tid; t < Tq; t += 256) {
        if (uv[t] > th) { sgt += col[t]; cgt += 1.f; }
    }
    float sb = 0.f;
    for (int i = tid; i < Kq; i += 256)
        sb += col[g_idx_bkg[b * Kq + i]];

    redA[tid] = sgt;
    redB[tid] = sb;
    redC[tid] = cgt;
    __syncthreads();
    for (int s = 128; s > 0; s >>= 1) {
        if (tid < s) {
            redA[tid] += redA[tid + s];
            redB[tid] += redB[tid + s];
            redC[tid] += redC[tid + s];
        }
        __syncthreads();
    }
    if (tid == 0) {
        float total = redA[0] + ((float)Kq - redC[0]) * thf;
        g_sa[bc] = total / (float)Kq;
        g_sb[bc] = redB[0] / (float)Kq;
    }
}

// ---------------------------------------------------------------------------
// K5: softmax over C for score_act / score_bkg (one warp per batch).
// ---------------------------------------------------------------------------
__global__ __launch_bounds__(32) void k_softmax_scores(float* __restrict__ out)
{
    const int b = blockIdx.x;
    const int lane = threadIdx.x;
    float va = (lane < Cq) ? g_sa[b * Cq + lane] : -INFINITY;
    float vb = (lane < Cq) ? g_sb[b * Cq + lane] : -INFINITY;
    float ma = va, mb = vb;
#pragma unroll
    for (int off = 16; off > 0; off >>= 1) {
        ma = fmaxf(ma, __shfl_xor_sync(0xffffffffu, ma, off));
        mb = fmaxf(mb, __shfl_xor_sync(0xffffffffu, mb, off));
    }
    float ea = (lane < Cq) ? expf(va - ma) : 0.f;
    float eb = (lane < Cq) ? expf(vb - mb) : 0.f;
    float sa = ea, sb = eb;
#pragma unroll
    for (int off = 16; off > 0; off >>= 1) {
        sa += __shfl_xor_sync(0xffffffffu, sa, off);
        sb += __shfl_xor_sync(0xffffffffu, sb, off);
    }
    if (lane < Cq) {
        out[OFF_SA + b * Cq + lane] = ea / sa;
        out[OFF_SB + b * Cq + lane] = eb / sb;
    }
}

// ---------------------------------------------------------------------------
extern "C" void kernel_launch(void* const* d_in, const int* in_sizes, int n_in,
                              void* d_out, int out_size)
{
    const float* x   = (const float*)d_in[0];   // (B,T,F)
    const float* W   = (const float*)d_in[1];   // (C,F)
    const float* mk  = (const float*)d_in[2];   // (B,T,F)
    const float* sel = (const float*)d_in[3];   // (B,T)
    float* out = (float*)d_out;

    k_main<<<NROWS / 16, 256>>>((const ulonglong2*)x, (const ulonglong2*)mk,
                                (const ulonglong2*)W, out);
    k_select<<<Bq, 256>>>(sel);
    {
        dim3 grid(Bq * Kq, 2);
        k_gather<<<grid, 128>>>((const float4*)x, out);
    }
    k_scores<<<Bq * Cq, 256>>>();
    k_softmax_scores<<<Bq, 32>>>(out);
}

// round 3
// speedup vs baseline: 1.5735x; 1.5735x over previous
#include <cuda_runtime.h>
#include <math.h>

// Problem constants
#define Bq 16
#define Tq 750
#define Fq 4096
#define Cq 20
#define Kq 93           // T / 8
#define F4 (Fq/4)       // 1024 float4 per row
#define NROWS (Bq*Tq)   // 12000

// Output layout (concatenated in reference return order, float32)
#define OFF_SA   0L
#define OFF_SB   320L
#define OFF_FA   640L
#define OFF_FB   (OFF_FA + (long)Bq*Kq*Fq)
#define OFF_FEAT (OFF_FB + (long)Bq*Kq*Fq)
#define OFF_CS   (OFF_FEAT + (long)NROWS*Fq)

// Scratch (static device globals; no runtime allocation)
__device__ float g_cas[NROWS*Cq];
__device__ float g_mag[NROWS];
__device__ int   g_idx_act[Bq*Kq];
__device__ int   g_idx_bkg[Bq*Kq];
__device__ float g_sa[Bq*Cq];
__device__ float g_sb[Bq*Cq];

// Monotone float <-> uint order map (total order)
__device__ __forceinline__ unsigned int fmap(float f)
{
    unsigned int u = __float_as_uint(f);
    return (u & 0x80000000u) ? ~u : (u | 0x80000000u);
}
__device__ __forceinline__ float funmap(unsigned int u)
{
    return (u & 0x80000000u) ? __uint_as_float(u ^ 0x80000000u)
                             : __uint_as_float(~u);
}

// Block-wide k-th largest (1-based k) over mapped uints in smem.
// 4-bit radix descent: 8 steps, 16-bin histogram. All threads return same value.
__device__ unsigned int kth_largest(const unsigned int* __restrict__ v, int n,
                                    int k, int* s_hist, int tid, int nthr)
{
    unsigned int prefix = 0;
    for (int shift = 28; shift >= 0; shift -= 4) {
        if (tid < 16) s_hist[tid] = 0;
        __syncthreads();
        const unsigned int mask_hi = (shift == 28) ? 0u : (0xFFFFFFFFu << (shift + 4));
        for (int t = tid; t < n; t += nthr) {
            unsigned int x = v[t];
            if ((x & mask_hi) == prefix)
                atomicAdd(&s_hist[(x >> shift) & 15], 1);
        }
        __syncthreads();
        // all threads walk the histogram identically (same shared data)
        int kk = k;
        int d = 15;
        for (; d > 0; d--) {
            int c = s_hist[d];
            if (kk <= c) break;
            kk -= c;
        }
        prefix |= (unsigned int)d << shift;
        k = kk;
        __syncthreads();
    }
    return prefix;
}

// ---------------------------------------------------------------------------
// K1: fused stream kernel. Each warp owns 4 rows (b,t):
//   masked GEMM (20 classes, scalar fp32 accumulators), sumsq, features copy,
//   per-row softmax -> cas_softmax; raw cas + mag -> scratch.
// 4 rows/warp amortizes W loads (L1-bandwidth bound component).
// ---------------------------------------------------------------------------
__global__ __launch_bounds__(256) void k_main(const float4* __restrict__ x4,
                                              const float4* __restrict__ m4,
                                              const float4* __restrict__ w4,
                                              float* __restrict__ out)
{
    const int warp = (blockIdx.x * blockDim.x + threadIdx.x) >> 5;
    const int lane = threadIdx.x & 31;
    const int r0 = warp * 4;
    if (r0 >= NROWS) return;

    const float4* __restrict__ xb = x4 + (long)r0 * F4;
    const float4* __restrict__ mb = m4 + (long)r0 * F4;
    float4* __restrict__ fb = reinterpret_cast<float4*>(out + OFF_FEAT) + (long)r0 * F4;

    float acc[4][Cq];
#pragma unroll
    for (int r = 0; r < 4; r++)
#pragma unroll
        for (int c = 0; c < Cq; c++) acc[r][c] = 0.f;
    float sq[4] = {0.f, 0.f, 0.f, 0.f};

    for (int i = 0; i < F4 / 32; i++) {
        const int j = lane + 32 * i;
        float4 a0 = xb[j];
        float4 a1 = xb[j + F4];
        float4 a2 = xb[j + 2 * F4];
        float4 a3 = xb[j + 3 * F4];
        float4 q0 = mb[j];
        float4 q1 = mb[j + F4];
        float4 q2 = mb[j + 2 * F4];
        float4 q3 = mb[j + 3 * F4];
        fb[j]          = a0;
        fb[j + F4]     = a1;
        fb[j + 2 * F4] = a2;
        fb[j + 3 * F4] = a3;
        sq[0] = fmaf(a0.x,a0.x, fmaf(a0.y,a0.y, fmaf(a0.z,a0.z, fmaf(a0.w,a0.w, sq[0]))));
        sq[1] = fmaf(a1.x,a1.x, fmaf(a1.y,a1.y, fmaf(a1.z,a1.z, fmaf(a1.w,a1.w, sq[1]))));
        sq[2] = fmaf(a2.x,a2.x, fmaf(a2.y,a2.y, fmaf(a2.z,a2.z, fmaf(a2.w,a2.w, sq[2]))));
        sq[3] = fmaf(a3.x,a3.x, fmaf(a3.y,a3.y, fmaf(a3.z,a3.z, fmaf(a3.w,a3.w, sq[3]))));
        // masked products (reuse q registers)
        q0.x *= a0.x; q0.y *= a0.y; q0.z *= a0.z; q0.w *= a0.w;
        q1.x *= a1.x; q1.y *= a1.y; q1.z *= a1.z; q1.w *= a1.w;
        q2.x *= a2.x; q2.y *= a2.y; q2.z *= a2.z; q2.w *= a2.w;
        q3.x *= a3.x; q3.y *= a3.y; q3.z *= a3.z; q3.w *= a3.w;
#pragma unroll
        for (int c = 0; c < Cq; c++) {
            float4 w = w4[c * F4 + j];
            acc[0][c] = fmaf(q0.x,w.x, fmaf(q0.y,w.y, fmaf(q0.z,w.z, fmaf(q0.w,w.w, acc[0][c]))));
            acc[1][c] = fmaf(q1.x,w.x, fmaf(q1.y,w.y, fmaf(q1.z,w.z, fmaf(q1.w,w.w, acc[1][c]))));
            acc[2][c] = fmaf(q2.x,w.x, fmaf(q2.y,w.y, fmaf(q2.z,w.z, fmaf(q2.w,w.w, acc[2][c]))));
            acc[3][c] = fmaf(q3.x,w.x, fmaf(q3.y,w.y, fmaf(q3.z,w.z, fmaf(q3.w,w.w, acc[3][c]))));
        }
    }

    // warp tree reduction (butterfly)
#pragma unroll
    for (int off = 16; off > 0; off >>= 1) {
#pragma unroll
        for (int r = 0; r < 4; r++) {
            sq[r] += __shfl_xor_sync(0xffffffffu, sq[r], off);
#pragma unroll
            for (int c = 0; c < Cq; c++)
                acc[r][c] += __shfl_xor_sync(0xffffffffu, acc[r][c], off);
        }
    }

    // lane c (<20) takes class c
    float v[4] = {0.f, 0.f, 0.f, 0.f};
#pragma unroll
    for (int c = 0; c < Cq; c++) {
        if (lane == c) {
            v[0] = acc[0][c]; v[1] = acc[1][c];
            v[2] = acc[2][c]; v[3] = acc[3][c];
        }
    }

    // softmax over C=20 across lanes, per row
#pragma unroll
    for (int r = 0; r < 4; r++) {
        float mv = (lane < Cq) ? v[r] : -INFINITY;
#pragma unroll
        for (int off = 16; off > 0; off >>= 1)
            mv = fmaxf(mv, __shfl_xor_sync(0xffffffffu, mv, off));
        float e = (lane < Cq) ? expf(v[r] - mv) : 0.f;
        float s = e;
#pragma unroll
        for (int off = 16; off > 0; off >>= 1)
            s += __shfl_xor_sync(0xffffffffu, s, off);
        if (lane < Cq) {
            out[OFF_CS + (long)(r0 + r) * Cq + lane] = e / s;
            g_cas[(r0 + r) * Cq + lane] = v[r];
        }
        if (lane == 0) g_mag[r0 + r] = sqrtf(sq[r]);
    }
}

// ---------------------------------------------------------------------------
// K2: per-batch selection. Radix-select the 93rd-largest threshold, then
// stable rank-count ONLY the ~93 candidates (exact jax.lax.top_k order).
// ---------------------------------------------------------------------------
__global__ __launch_bounds__(256) void k_select(const float* __restrict__ sel)
{
    const int b = blockIdx.x;
    const int tid = threadIdx.x;
    __shared__ unsigned int ua[Tq];
    __shared__ unsigned int ub[Tq];
    __shared__ float red[256];
    __shared__ int s_hist[16];

    // load mags, block max
    float lmax = -INFINITY;
    for (int t = tid; t < Tq; t += 256) {
        float m = g_mag[b * Tq + t];
        ua[t] = __float_as_uint(m);
        lmax = fmaxf(lmax, m);
    }
    red[tid] = lmax;
    __syncthreads();
    for (int s = 128; s > 0; s >>= 1) {
        if (tid < s) red[tid] = fmaxf(red[tid], red[tid + s]);
        __syncthreads();
    }
    const float mx = red[0];
    __syncthreads();

    for (int t = tid; t < Tq; t += 256) {
        float m = __uint_as_float(ua[t]);
        float s = sel[b * Tq + t];
        float va = m * s + 0.0f;
        float vr = (mx - m) * s + 0.0f;
        ua[t] = fmap(va);
        ub[t] = fmap(vr);
    }
    __syncthreads();

    const unsigned int thA = kth_largest(ua, Tq, Kq, s_hist, tid, 256);
    const unsigned int thB = kth_largest(ub, Tq, Kq, s_hist, tid, 256);

    for (int t = tid; t < Tq; t += 256) {
        unsigned int xA = ua[t];
        unsigned int xB = ub[t];
        if (xA >= thA) {
            int r = 0;
            for (int j = 0; j < Tq; j++) {
                unsigned int u = ua[j];
                r += (u > xA) || (u == xA && j < t);
            }
            if (r < Kq) g_idx_act[b * Kq + r] = t;
        }
        if (xB >= thB) {
            int r = 0;
            for (int j = 0; j < Tq; j++) {
                unsigned int u = ub[j];
                r += (u > xB) || (u == xB && j < t);
            }
            if (r < Kq) g_idx_bkg[b * Kq + r] = t;
        }
    }
}

// ---------------------------------------------------------------------------
// K3: gather feat_act / feat_bkg rows from x.
// ---------------------------------------------------------------------------
__global__ __launch_bounds__(128) void k_gather(const float4* __restrict__ x4,
                                                float* __restrict__ out)
{
    const int i = blockIdx.x;           // b*93 + k
    const int b = i / Kq;
    const int t = (blockIdx.y == 0) ? g_idx_act[i] : g_idx_bkg[i];
    const float4* __restrict__ src = x4 + ((long)(b * Tq + t)) * F4;
    float4* __restrict__ dst =
        reinterpret_cast<float4*>(out + (blockIdx.y == 0 ? OFF_FA : OFF_FB)) + (long)i * F4;
#pragma unroll
    for (int j = threadIdx.x; j < F4; j += 128) dst[j] = src[j];
}

// ---------------------------------------------------------------------------
// K4: per-(b,c): sum of top-93 cas over T via threshold (order-independent),
// plus mean of cas at idx_bkg.
// ---------------------------------------------------------------------------
__global__ __launch_bounds__(256) void k_scores()
{
    const int bc = blockIdx.x;          // b*20 + c
    const int b = bc / Cq;
    const int c = bc % Cq;
    const int tid = threadIdx.x;
    __shared__ float col[Tq];
    __shared__ unsigned int uv[Tq];
    __shared__ float redA[256];
    __shared__ float redB[256];
    __shared__ float redC[256];
    __shared__ int s_hist[16];

    for (int t = tid; t < Tq; t += 256) {
        float v = g_cas[(b * Tq + t) * Cq + c];
        col[t] = v;
        uv[t] = fmap(v);
    }
    __syncthreads();

    const unsigned int th = kth_largest(uv, Tq, Kq, s_hist, tid, 256);
    const float thf = funmap(th);

    float sgt = 0.f;   // sum of strictly-greater-than-threshold values
    float cgt = 0.f;   // count of them
    for (int t = tid; t < Tq; t += 256) {
        if (uv[t] > th) { sgt += col[t]; cgt += 1.f; }
    }
    float sb = 0.f;
    for (int i = tid; i < Kq; i += 256)
        sb += col[g_idx_bkg[b * Kq + i]];

    redA[tid] = sgt;
    redB[tid] = sb;
    redC[tid] = cgt;
    __syncthreads();
    for (int s = 128; s > 0; s >>= 1) {
        if (tid < s) {
            redA[tid] += redA[tid + s];
            redB[tid] += redB[tid + s];
            redC[tid] += redC[tid + s];
        }
        __syncthreads();
    }
    if (tid == 0) {
        float total = redA[0] + ((float)Kq - redC[0]) * thf;
        g_sa[bc] = total / (float)Kq;
        g_sb[bc] = redB[0] / (float)Kq;
    }
}

// ---------------------------------------------------------------------------
// K5: softmax over C for score_act / score_bkg (one warp per batch).
// ---------------------------------------------------------------------------
__global__ __launch_bounds__(32) void k_softmax_scores(float* __restrict__ out)
{
    const int b = blockIdx.x;
    const int lane = threadIdx.x;
    float va = (lane < Cq) ? g_sa[b * Cq + lane] : -INFINITY;
    float vb = (lane < Cq) ? g_sb[b * Cq + lane] : -INFINITY;
    float ma = va, mb = vb;
#pragma unroll
    for (int off = 16; off > 0; off >>= 1) {
        ma = fmaxf(ma, __shfl_xor_sync(0xffffffffu, ma, off));
        mb = fmaxf(mb, __shfl_xor_sync(0xffffffffu, mb, off));
    }
    float ea = (lane < Cq) ? expf(va - ma) : 0.f;
    float eb = (lane < Cq) ? expf(vb - mb) : 0.f;
    float sa = ea, sb = eb;
#pragma unroll
    for (int off = 16; off > 0; off >>= 1) {
        sa += __shfl_xor_sync(0xffffffffu, sa, off);
        sb += __shfl_xor_sync(0xffffffffu, sb, off);
    }
    if (lane < Cq) {
        out[OFF_SA + b * Cq + lane] = ea / sa;
        out[OFF_SB + b * Cq + lane] = eb / sb;
    }
}

// ---------------------------------------------------------------------------
extern "C" void kernel_launch(void* const* d_in, const int* in_sizes, int n_in,
                              void* d_out, int out_size)
{
    const float* x   = (const float*)d_in[0];   // (B,T,F)
    const float* W   = (const float*)d_in[1];   // (C,F)
    const float* mk  = (const float*)d_in[2];   // (B,T,F)
    const float* sel = (const float*)d_in[3];   // (B,T)
    float* out = (float*)d_out;

    k_main<<<NROWS / 4 / 8, 256>>>((const float4*)x, (const float4*)mk,
                                   (const float4*)W, out);
    k_select<<<Bq, 256>>>(sel);
    {
        dim3 grid(Bq * Kq, 2);
        k_gather<<<grid, 128>>>((const float4*)x, out);
    }
    k_scores<<<Bq * Cq, 256>>>();
    k_softmax_scores<<<Bq, 32>>>(out);
}

// round 4
// speedup vs baseline: 3.7801x; 2.4023x over previous
#include <cuda_runtime.h>
#include <math.h>

// Problem constants
#define Bq 16
#define Tq 750
#define Fq 4096
#define Cq 20
#define Kq 93           // T / 8
#define F4 (Fq/4)       // 1024 float4 per row
#define NROWS (Bq*Tq)   // 12000

#define CHUNK 128       // float4 per F-chunk (8 chunks per row)
#define ROWS_PER_BLOCK 16

// Output layout (concatenated in reference return order, float32)
#define OFF_SA   0L
#define OFF_SB   320L
#define OFF_FA   640L
#define OFF_FB   (OFF_FA + (long)Bq*Kq*Fq)
#define OFF_FEAT (OFF_FB + (long)Bq*Kq*Fq)
#define OFF_CS   (OFF_FEAT + (long)NROWS*Fq)

// Scratch (static device globals; no runtime allocation)
__device__ float g_cas[NROWS*Cq];
__device__ float g_mag[NROWS];
__device__ int   g_idx_act[Bq*Kq];
__device__ int   g_idx_bkg[Bq*Kq];
__device__ float g_sa[Bq*Cq];
__device__ float g_sb[Bq*Cq];

// Monotone float <-> uint order map (total order)
__device__ __forceinline__ unsigned int fmap(float f)
{
    unsigned int u = __float_as_uint(f);
    return (u & 0x80000000u) ? ~u : (u | 0x80000000u);
}
__device__ __forceinline__ float funmap(unsigned int u)
{
    return (u & 0x80000000u) ? __uint_as_float(u ^ 0x80000000u)
                             : __uint_as_float(~u);
}

// Block-wide k-th largest (1-based k) over mapped uints in smem.
// 4-bit radix descent: 8 steps, 16-bin histogram. All threads return same value.
__device__ unsigned int kth_largest(const unsigned int* __restrict__ v, int n,
                                    int k, int* s_hist, int tid, int nthr)
{
    unsigned int prefix = 0;
    for (int shift = 28; shift >= 0; shift -= 4) {
        if (tid < 16) s_hist[tid] = 0;
        __syncthreads();
        const unsigned int mask_hi = (shift == 28) ? 0u : (0xFFFFFFFFu << (shift + 4));
        for (int t = tid; t < n; t += nthr) {
            unsigned int x = v[t];
            if ((x & mask_hi) == prefix)
                atomicAdd(&s_hist[(x >> shift) & 15], 1);
        }
        __syncthreads();
        int kk = k;
        int d = 15;
        for (; d > 0; d--) {
            int c = s_hist[d];
            if (kk <= c) break;
            kk -= c;
        }
        prefix |= (unsigned int)d << shift;
        k = kk;
        __syncthreads();
    }
    return prefix;
}

// ---------------------------------------------------------------------------
// K1: fused stream kernel. Block = 256 threads = 8 warps = 16 rows (2/warp).
// F processed in 8 chunks of 128 float4; per chunk the block stages the W
// slice (20x128 float4 = 40KB) in smem so all 8 warps reuse one L2 read.
//   masked GEMM (20 classes), sumsq, features copy,
//   per-row softmax -> cas_softmax; raw cas + mag -> scratch.
// ---------------------------------------------------------------------------
__global__ __launch_bounds__(256, 2) void k_main(const float4* __restrict__ x4,
                                                 const float4* __restrict__ m4,
                                                 const float4* __restrict__ w4,
                                                 float* __restrict__ out)
{
    __shared__ float4 wsh[Cq * CHUNK];   // 40 KB

    const int tid  = threadIdx.x;
    const int wid  = tid >> 5;
    const int lane = tid & 31;
    const int r0 = blockIdx.x * ROWS_PER_BLOCK + wid * 2;  // warp's first row
    const int r1 = r0 + 1;

    const float4* __restrict__ xa = x4 + (long)r0 * F4;
    const float4* __restrict__ xb = x4 + (long)r1 * F4;
    const float4* __restrict__ ma = m4 + (long)r0 * F4;
    const float4* __restrict__ mb = m4 + (long)r1 * F4;
    float4* __restrict__ fa = reinterpret_cast<float4*>(out + OFF_FEAT) + (long)r0 * F4;
    float4* __restrict__ fb = reinterpret_cast<float4*>(out + OFF_FEAT) + (long)r1 * F4;

    float acc0[Cq], acc1[Cq];
#pragma unroll
    for (int c = 0; c < Cq; c++) { acc0[c] = 0.f; acc1[c] = 0.f; }
    float sq0 = 0.f, sq1 = 0.f;

    for (int ch = 0; ch < F4 / CHUNK; ch++) {
        const int jc = ch * CHUNK;
        // cooperative stage of W slice: 2560 float4, 10 per thread, coalesced
        __syncthreads();
#pragma unroll
        for (int q = 0; q < (Cq * CHUNK) / 256; q++) {
            int idx = tid + 256 * q;
            wsh[idx] = w4[(idx >> 7) * F4 + jc + (idx & (CHUNK - 1))];
        }
        __syncthreads();

#pragma unroll
        for (int ii = 0; ii < CHUNK / 32; ii++) {
            const int jj = lane + 32 * ii;      // within chunk
            const int j  = jc + jj;             // within row
            float4 a0 = xa[j];
            float4 a1 = xb[j];
            float4 q0 = ma[j];
            float4 q1 = mb[j];
            fa[j] = a0;
            fb[j] = a1;
            sq0 = fmaf(a0.x,a0.x, fmaf(a0.y,a0.y, fmaf(a0.z,a0.z, fmaf(a0.w,a0.w, sq0))));
            sq1 = fmaf(a1.x,a1.x, fmaf(a1.y,a1.y, fmaf(a1.z,a1.z, fmaf(a1.w,a1.w, sq1))));
            q0.x *= a0.x; q0.y *= a0.y; q0.z *= a0.z; q0.w *= a0.w;
            q1.x *= a1.x; q1.y *= a1.y; q1.z *= a1.z; q1.w *= a1.w;
#pragma unroll
            for (int c = 0; c < Cq; c++) {
                float4 w = wsh[c * CHUNK + jj];
                acc0[c] = fmaf(q0.x,w.x, fmaf(q0.y,w.y, fmaf(q0.z,w.z, fmaf(q0.w,w.w, acc0[c]))));
                acc1[c] = fmaf(q1.x,w.x, fmaf(q1.y,w.y, fmaf(q1.z,w.z, fmaf(q1.w,w.w, acc1[c]))));
            }
        }
    }

    // warp tree reduction (butterfly)
#pragma unroll
    for (int off = 16; off > 0; off >>= 1) {
        sq0 += __shfl_xor_sync(0xffffffffu, sq0, off);
        sq1 += __shfl_xor_sync(0xffffffffu, sq1, off);
#pragma unroll
        for (int c = 0; c < Cq; c++) {
            acc0[c] += __shfl_xor_sync(0xffffffffu, acc0[c], off);
            acc1[c] += __shfl_xor_sync(0xffffffffu, acc1[c], off);
        }
    }

    // lane c (<20) takes class c
    float v0 = 0.f, v1 = 0.f;
#pragma unroll
    for (int c = 0; c < Cq; c++) {
        if (lane == c) { v0 = acc0[c]; v1 = acc1[c]; }
    }

    // softmax over C=20 across lanes
    float mm0 = (lane < Cq) ? v0 : -INFINITY;
    float mm1 = (lane < Cq) ? v1 : -INFINITY;
#pragma unroll
    for (int off = 16; off > 0; off >>= 1) {
        mm0 = fmaxf(mm0, __shfl_xor_sync(0xffffffffu, mm0, off));
        mm1 = fmaxf(mm1, __shfl_xor_sync(0xffffffffu, mm1, off));
    }
    float e0 = (lane < Cq) ? expf(v0 - mm0) : 0.f;
    float e1 = (lane < Cq) ? expf(v1 - mm1) : 0.f;
    float s0 = e0, s1 = e1;
#pragma unroll
    for (int off = 16; off > 0; off >>= 1) {
        s0 += __shfl_xor_sync(0xffffffffu, s0, off);
        s1 += __shfl_xor_sync(0xffffffffu, s1, off);
    }
    if (lane < Cq) {
        out[OFF_CS + (long)r0 * Cq + lane] = e0 / s0;
        out[OFF_CS + (long)r1 * Cq + lane] = e1 / s1;
        g_cas[r0 * Cq + lane] = v0;
        g_cas[r1 * Cq + lane] = v1;
    }
    if (lane == 0) {
        g_mag[r0] = sqrtf(sq0);
        g_mag[r1] = sqrtf(sq1);
    }
}

// ---------------------------------------------------------------------------
// K2: per-batch selection. Radix-select the 93rd-largest threshold, then
// stable rank-count ONLY the ~93 candidates (exact jax.lax.top_k order).
// ---------------------------------------------------------------------------
__global__ __launch_bounds__(256) void k_select(const float* __restrict__ sel)
{
    const int b = blockIdx.x;
    const int tid = threadIdx.x;
    __shared__ unsigned int ua[Tq];
    __shared__ unsigned int ub[Tq];
    __shared__ float red[256];
    __shared__ int s_hist[16];

    float lmax = -INFINITY;
    for (int t = tid; t < Tq; t += 256) {
        float m = g_mag[b * Tq + t];
        ua[t] = __float_as_uint(m);
        lmax = fmaxf(lmax, m);
    }
    red[tid] = lmax;
    __syncthreads();
    for (int s = 128; s > 0; s >>= 1) {
        if (tid < s) red[tid] = fmaxf(red[tid], red[tid + s]);
        __syncthreads();
    }
    const float mx = red[0];
    __syncthreads();

    for (int t = tid; t < Tq; t += 256) {
        float m = __uint_as_float(ua[t]);
        float s = sel[b * Tq + t];
        float va = m * s + 0.0f;
        float vr = (mx - m) * s + 0.0f;
        ua[t] = fmap(va);
        ub[t] = fmap(vr);
    }
    __syncthreads();

    const unsigned int thA = kth_largest(ua, Tq, Kq, s_hist, tid, 256);
    const unsigned int thB = kth_largest(ub, Tq, Kq, s_hist, tid, 256);

    for (int t = tid; t < Tq; t += 256) {
        unsigned int xA = ua[t];
        unsigned int xB = ub[t];
        if (xA >= thA) {
            int r = 0;
            for (int j = 0; j < Tq; j++) {
                unsigned int u = ua[j];
                r += (u > xA) || (u == xA && j < t);
            }
            if (r < Kq) g_idx_act[b * Kq + r] = t;
        }
        if (xB >= thB) {
            int r = 0;
            for (int j = 0; j < Tq; j++) {
                unsigned int u = ub[j];
                r += (u > xB) || (u == xB && j < t);
            }
            if (r < Kq) g_idx_bkg[b * Kq + r] = t;
        }
    }
}

// ---------------------------------------------------------------------------
// K3: gather feat_act / feat_bkg rows from x.
// ---------------------------------------------------------------------------
__global__ __launch_bounds__(128) void k_gather(const float4* __restrict__ x4,
                                                float* __restrict__ out)
{
    const int i = blockIdx.x;           // b*93 + k
    const int b = i / Kq;
    const int t = (blockIdx.y == 0) ? g_idx_act[i] : g_idx_bkg[i];
    const float4* __restrict__ src = x4 + ((long)(b * Tq + t)) * F4;
    float4* __restrict__ dst =
        reinterpret_cast<float4*>(out + (blockIdx.y == 0 ? OFF_FA : OFF_FB)) + (long)i * F4;
#pragma unroll
    for (int j = threadIdx.x; j < F4; j += 128) dst[j] = src[j];
}

// ---------------------------------------------------------------------------
// K4: per-(b,c): sum of top-93 cas over T via threshold (order-independent),
// plus mean of cas at idx_bkg.
// ---------------------------------------------------------------------------
__global__ __launch_bounds__(256) void k_scores()
{
    const int bc = blockIdx.x;          // b*20 + c
    const int b = bc / Cq;
    const int c = bc % Cq;
    const int tid = threadIdx.x;
    __shared__ float col[Tq];
    __shared__ unsigned int uv[Tq];
    __shared__ float redA[256];
    __shared__ float redB[256];
    __shared__ float redC[256];
    __shared__ int s_hist[16];

    for (int t = tid; t < Tq; t += 256) {
        float v = g_cas[(b * Tq + t) * Cq + c];
        col[t] = v;
        uv[t] = fmap(v);
    }
    __syncthreads();

    const unsigned int th = kth_largest(uv, Tq, Kq, s_hist, tid, 256);
    const float thf = funmap(th);

    float sgt = 0.f;
    float cgt = 0.f;
    for (int t = tid; t < Tq; t += 256) {
        if (uv[t] > th) { sgt += col[t]; cgt += 1.f; }
    }
    float sb = 0.f;
    for (int i = tid; i < Kq; i += 256)
        sb += col[g_idx_bkg[b * Kq + i]];

    redA[tid] = sgt;
    redB[tid] = sb;
    redC[tid] = cgt;
    __syncthreads();
    for (int s = 128; s > 0; s >>= 1) {
        if (tid < s) {
            redA[tid] += redA[tid + s];
            redB[tid] += redB[tid + s];
            redC[tid] += redC[tid + s];
        }
        __syncthreads();
    }
    if (tid == 0) {
        float total = redA[0] + ((float)Kq - redC[0]) * thf;
        g_sa[bc] = total / (float)Kq;
        g_sb[bc] = redB[0] / (float)Kq;
    }
}

// ---------------------------------------------------------------------------
// K5: softmax over C for score_act / score_bkg (one warp per batch).
// ---------------------------------------------------------------------------
__global__ __launch_bounds__(32) void k_softmax_scores(float* __restrict__ out)
{
    const int b = blockIdx.x;
    const int lane = threadIdx.x;
    float va = (lane < Cq) ? g_sa[b * Cq + lane] : -INFINITY;
    float vb = (lane < Cq) ? g_sb[b * Cq + lane] : -INFINITY;
    float ma = va, mb = vb;
#pragma unroll
    for (int off = 16; off > 0; off >>= 1) {
        ma = fmaxf(ma, __shfl_xor_sync(0xffffffffu, ma, off));
        mb = fmaxf(mb, __shfl_xor_sync(0xffffffffu, mb, off));
    }
    float ea = (lane < Cq) ? expf(va - ma) : 0.f;
    float eb = (lane < Cq) ? expf(vb - mb) : 0.f;
    float sa = ea, sb = eb;
#pragma unroll
    for (int off = 16; off > 0; off >>= 1) {
        sa += __shfl_xor_sync(0xffffffffu, sa, off);
        sb += __shfl_xor_sync(0xffffffffu, sb, off);
    }
    if (lane < Cq) {
        out[OFF_SA + b * Cq + lane] = ea / sa;
        out[OFF_SB + b * Cq + lane] = eb / sb;
    }
}

// ---------------------------------------------------------------------------
extern "C" void kernel_launch(void* const* d_in, const int* in_sizes, int n_in,
                              void* d_out, int out_size)
{
    const float* x   = (const float*)d_in[0];   // (B,T,F)
    const float* W   = (const float*)d_in[1];   // (C,F)
    const float* mk  = (const float*)d_in[2];   // (B,T,F)
    const float* sel = (const float*)d_in[3];   // (B,T)
    float* out = (float*)d_out;

    k_main<<<NROWS / ROWS_PER_BLOCK, 256>>>((const float4*)x, (const float4*)mk,
                                            (const float4*)W, out);
    k_select<<<Bq, 256>>>(sel);
    {
        dim3 grid(Bq * Kq, 2);
        k_gather<<<grid, 128>>>((const float4*)x, out);
    }
    k_scores<<<Bq * Cq, 256>>>();
    k_softmax_scores<<<Bq, 32>>>(out);
}

// round 5
// speedup vs baseline: 4.1425x; 1.0959x over previous
#include <cuda_runtime.h>
#include <math.h>

// Problem constants
#define Bq 16
#define Tq 750
#define Fq 4096
#define Cq 20
#define Kq 93           // T / 8
#define F4 (Fq/4)       // 1024 float4 per row
#define NROWS (Bq*Tq)   // 12000

#define CHUNK 64        // float4 per F-chunk (16 chunks per row)
#define ROWS_PER_BLOCK 16

// Output layout (concatenated in reference return order, float32)
#define OFF_SA   0L
#define OFF_SB   320L
#define OFF_FA   640L
#define OFF_FB   (OFF_FA + (long)Bq*Kq*Fq)
#define OFF_FEAT (OFF_FB + (long)Bq*Kq*Fq)
#define OFF_CS   (OFF_FEAT + (long)NROWS*Fq)

// Scratch (static device globals; no runtime allocation)
__device__ float g_cas[NROWS*Cq];
__device__ float g_mag[NROWS];
__device__ int   g_idx_act[Bq*Kq];
__device__ int   g_idx_bkg[Bq*Kq];
__device__ float g_sa[Bq*Cq];
__device__ float g_sb[Bq*Cq];

// Monotone float <-> uint order map (total order)
__device__ __forceinline__ unsigned int fmap(float f)
{
    unsigned int u = __float_as_uint(f);
    return (u & 0x80000000u) ? ~u : (u | 0x80000000u);
}
__device__ __forceinline__ float funmap(unsigned int u)
{
    return (u & 0x80000000u) ? __uint_as_float(u ^ 0x80000000u)
                             : __uint_as_float(~u);
}

__device__ __forceinline__ void bar_named(int id)
{
    asm volatile("bar.sync %0, 128;" :: "r"(id) : "memory");
}

// 128-thread k-th largest using a named barrier (two instances run
// concurrently in one 256-thread block). 4-bit radix descent.
__device__ unsigned int kth_largest_h(const unsigned int* __restrict__ v, int n,
                                      int k, int* s_hist, int ltid, int barid)
{
    unsigned int prefix = 0;
    for (int shift = 28; shift >= 0; shift -= 4) {
        if (ltid < 16) s_hist[ltid] = 0;
        bar_named(barid);
        const unsigned int mask_hi = (shift == 28) ? 0u : (0xFFFFFFFFu << (shift + 4));
        for (int t = ltid; t < n; t += 128) {
            unsigned int x = v[t];
            if ((x & mask_hi) == prefix)
                atomicAdd(&s_hist[(x >> shift) & 15], 1);
        }
        bar_named(barid);
        int kk = k;
        int d = 15;
        for (; d > 0; d--) {
            int c = s_hist[d];
            if (kk <= c) break;
            kk -= c;
        }
        prefix |= (unsigned int)d << shift;
        k = kk;
        bar_named(barid);
    }
    return prefix;
}

// ---------------------------------------------------------------------------
// K1: fused stream kernel. Block = 256 threads = 8 warps = 16 rows (2/warp).
// F processed in 16 chunks of 64 float4; W slice (20x64 float4 = 20KB) is
// cp.async-prefetched into a ping-pong smem buffer one chunk ahead, so the
// W-load latency is hidden behind compute.
// ---------------------------------------------------------------------------
__global__ __launch_bounds__(256, 2) void k_main(const float4* __restrict__ x4,
                                                 const float4* __restrict__ m4,
                                                 const float4* __restrict__ w4,
                                                 float* __restrict__ out)
{
    __shared__ float4 wsh[2][Cq * CHUNK];   // 2 x 20 KB

    const int tid  = threadIdx.x;
    const int wid  = tid >> 5;
    const int lane = tid & 31;
    const int r0 = blockIdx.x * ROWS_PER_BLOCK + wid * 2;
    const int r1 = r0 + 1;

    const float4* __restrict__ xa = x4 + (long)r0 * F4;
    const float4* __restrict__ xb = x4 + (long)r1 * F4;
    const float4* __restrict__ ma = m4 + (long)r0 * F4;
    const float4* __restrict__ mb = m4 + (long)r1 * F4;
    float4* __restrict__ fa = reinterpret_cast<float4*>(out + OFF_FEAT) + (long)r0 * F4;
    float4* __restrict__ fb = reinterpret_cast<float4*>(out + OFF_FEAT) + (long)r1 * F4;

    float acc0[Cq], acc1[Cq];
#pragma unroll
    for (int c = 0; c < Cq; c++) { acc0[c] = 0.f; acc1[c] = 0.f; }
    float sq0 = 0.f, sq1 = 0.f;

    // stage chunk ch of W into buffer buf via cp.async (no regs, no wait)
    auto stage = [&](int ch, int buf) {
        const int jc = ch * CHUNK;
#pragma unroll
        for (int q = 0; q < (Cq * CHUNK) / 256; q++) {   // 5 per thread
            int idx = tid + 256 * q;
            const float4* src = &w4[(idx >> 6) * F4 + jc + (idx & (CHUNK - 1))];
            unsigned int dst = (unsigned int)__cvta_generic_to_shared(&wsh[buf][idx]);
            asm volatile("cp.async.cg.shared.global [%0], [%1], 16;"
                         :: "r"(dst), "l"(src));
        }
        asm volatile("cp.async.commit_group;");
    };

    stage(0, 0);

    for (int ch = 0; ch < F4 / CHUNK; ch++) {
        const int buf = ch & 1;
        asm volatile("cp.async.wait_group 0;");
        __syncthreads();            // all copies visible; prior reads of other buf done
        if (ch + 1 < F4 / CHUNK) stage(ch + 1, buf ^ 1);

        const int jc = ch * CHUNK;
#pragma unroll
        for (int ii = 0; ii < CHUNK / 32; ii++) {
            const int jj = lane + 32 * ii;
            const int j  = jc + jj;
            float4 a0 = xa[j];
            float4 a1 = xb[j];
            float4 q0 = ma[j];
            float4 q1 = mb[j];
            fa[j] = a0;
            fb[j] = a1;
            sq0 = fmaf(a0.x,a0.x, fmaf(a0.y,a0.y, fmaf(a0.z,a0.z, fmaf(a0.w,a0.w, sq0))));
            sq1 = fmaf(a1.x,a1.x, fmaf(a1.y,a1.y, fmaf(a1.z,a1.z, fmaf(a1.w,a1.w, sq1))));
            q0.x *= a0.x; q0.y *= a0.y; q0.z *= a0.z; q0.w *= a0.w;
            q1.x *= a1.x; q1.y *= a1.y; q1.z *= a1.z; q1.w *= a1.w;
#pragma unroll
            for (int c = 0; c < Cq; c++) {
                float4 w = wsh[buf][c * CHUNK + jj];
                acc0[c] = fmaf(q0.x,w.x, fmaf(q0.y,w.y, fmaf(q0.z,w.z, fmaf(q0.w,w.w, acc0[c]))));
                acc1[c] = fmaf(q1.x,w.x, fmaf(q1.y,w.y, fmaf(q1.z,w.z, fmaf(q1.w,w.w, acc1[c]))));
            }
        }
    }

    // warp tree reduction (butterfly)
#pragma unroll
    for (int off = 16; off > 0; off >>= 1) {
        sq0 += __shfl_xor_sync(0xffffffffu, sq0, off);
        sq1 += __shfl_xor_sync(0xffffffffu, sq1, off);
#pragma unroll
        for (int c = 0; c < Cq; c++) {
            acc0[c] += __shfl_xor_sync(0xffffffffu, acc0[c], off);
            acc1[c] += __shfl_xor_sync(0xffffffffu, acc1[c], off);
        }
    }

    float v0 = 0.f, v1 = 0.f;
#pragma unroll
    for (int c = 0; c < Cq; c++) {
        if (lane == c) { v0 = acc0[c]; v1 = acc1[c]; }
    }

    float mm0 = (lane < Cq) ? v0 : -INFINITY;
    float mm1 = (lane < Cq) ? v1 : -INFINITY;
#pragma unroll
    for (int off = 16; off > 0; off >>= 1) {
        mm0 = fmaxf(mm0, __shfl_xor_sync(0xffffffffu, mm0, off));
        mm1 = fmaxf(mm1, __shfl_xor_sync(0xffffffffu, mm1, off));
    }
    float e0 = (lane < Cq) ? expf(v0 - mm0) : 0.f;
    float e1 = (lane < Cq) ? expf(v1 - mm1) : 0.f;
    float s0 = e0, s1 = e1;
#pragma unroll
    for (int off = 16; off > 0; off >>= 1) {
        s0 += __shfl_xor_sync(0xffffffffu, s0, off);
        s1 += __shfl_xor_sync(0xffffffffu, s1, off);
    }
    if (lane < Cq) {
        out[OFF_CS + (long)r0 * Cq + lane] = e0 / s0;
        out[OFF_CS + (long)r1 * Cq + lane] = e1 / s1;
        g_cas[r0 * Cq + lane] = v0;
        g_cas[r1 * Cq + lane] = v1;
    }
    if (lane == 0) {
        g_mag[r0] = sqrtf(sq0);
        g_mag[r1] = sqrtf(sq1);
    }
}

// ---------------------------------------------------------------------------
// K2: per-batch selection. Halves of the block process the act and bkg lists
// concurrently (named barriers). Radix threshold + stable rank-count of the
// ~93 candidates (exact jax.lax.top_k order).
// ---------------------------------------------------------------------------
__global__ __launch_bounds__(256) void k_select(const float* __restrict__ sel)
{
    const int b = blockIdx.x;
    const int tid = threadIdx.x;
    __shared__ unsigned int ua[Tq];
    __shared__ unsigned int ub[Tq];
    __shared__ float red[256];
    __shared__ int s_histA[16];
    __shared__ int s_histB[16];

    float lmax = -INFINITY;
    for (int t = tid; t < Tq; t += 256) {
        float m = g_mag[b * Tq + t];
        ua[t] = __float_as_uint(m);
        lmax = fmaxf(lmax, m);
    }
    red[tid] = lmax;
    __syncthreads();
    for (int s = 128; s > 0; s >>= 1) {
        if (tid < s) red[tid] = fmaxf(red[tid], red[tid + s]);
        __syncthreads();
    }
    const float mx = red[0];
    __syncthreads();

    for (int t = tid; t < Tq; t += 256) {
        float m = __uint_as_float(ua[t]);
        float s = sel[b * Tq + t];
        float va = m * s + 0.0f;
        float vr = (mx - m) * s + 0.0f;
        ua[t] = fmap(va);
        ub[t] = fmap(vr);
    }
    __syncthreads();

    if (tid < 128) {
        const unsigned int thA = kth_largest_h(ua, Tq, Kq, s_histA, tid, 1);
        for (int t = tid; t < Tq; t += 128) {
            unsigned int xA = ua[t];
            if (xA >= thA) {
                int r = 0;
                for (int j = 0; j < Tq; j++) {
                    unsigned int u = ua[j];
                    r += (u > xA) || (u == xA && j < t);
                }
                if (r < Kq) g_idx_act[b * Kq + r] = t;
            }
        }
    } else {
        const int lt = tid - 128;
        const unsigned int thB = kth_largest_h(ub, Tq, Kq, s_histB, lt, 2);
        for (int t = lt; t < Tq; t += 128) {
            unsigned int xB = ub[t];
            if (xB >= thB) {
                int r = 0;
                for (int j = 0; j < Tq; j++) {
                    unsigned int u = ub[j];
                    r += (u > xB) || (u == xB && j < t);
                }
                if (r < Kq) g_idx_bkg[b * Kq + r] = t;
            }
        }
    }
}

// ---------------------------------------------------------------------------
// K3: gather feat_act / feat_bkg rows from x.
// ---------------------------------------------------------------------------
__global__ __launch_bounds__(128) void k_gather(const float4* __restrict__ x4,
                                                float* __restrict__ out)
{
    const int i = blockIdx.x;           // b*93 + k
    const int b = i / Kq;
    const int t = (blockIdx.y == 0) ? g_idx_act[i] : g_idx_bkg[i];
    const float4* __restrict__ src = x4 + ((long)(b * Tq + t)) * F4;
    float4* __restrict__ dst =
        reinterpret_cast<float4*>(out + (blockIdx.y == 0 ? OFF_FA : OFF_FB)) + (long)i * F4;
#pragma unroll
    for (int j = threadIdx.x; j < F4; j += 128) dst[j] = src[j];
}

// ---------------------------------------------------------------------------
// K4: warp per (b,c), no barriers. Column lives in 24 regs/lane.
// 1-bit radix descent with __reduce_add_sync finds the 93rd-largest; sum of
// top-93 = sum(v>th) + (93 - n_gt)*th (order-independent). Plus idx_bkg mean.
// ---------------------------------------------------------------------------
#define NLOC 24   // ceil(750/32)
__global__ __launch_bounds__(256) void k_scores()
{
    const int gw = (blockIdx.x * 256 + threadIdx.x) >> 5;   // 0..319
    const int lane = threadIdx.x & 31;
    if (gw >= Bq * Cq) return;
    const int b = gw / Cq;
    const int c = gw % Cq;

    float lv[NLOC];
    unsigned int ul[NLOC];
#pragma unroll
    for (int i = 0; i < NLOC; i++) {
        int t = lane + 32 * i;
        if (t < Tq) {
            float v = g_cas[(b * Tq + t) * Cq + c];
            lv[i] = v;
            ul[i] = fmap(v);
        } else {
            lv[i] = 0.f;
            ul[i] = 0u;     // below every real mapped value
        }
    }

    // 1-bit radix descent, 32 passes, warp-collective
    unsigned int prefix = 0, mask = 0;
    int k = Kq;
    for (int bit = 31; bit >= 0; --bit) {
        const unsigned int m2   = mask | (1u << bit);
        const unsigned int test = prefix | (1u << bit);
        int cnt = 0;
#pragma unroll
        for (int i = 0; i < NLOC; i++)
            cnt += ((ul[i] & m2) == test);
        cnt = __reduce_add_sync(0xffffffffu, cnt);
        if (cnt >= k) prefix = test; else k -= cnt;
        mask = m2;
    }
    const unsigned int th = prefix;
    const float thf = funmap(th);

    float sgt = 0.f, cgt = 0.f;
#pragma unroll
    for (int i = 0; i < NLOC; i++) {
        if (ul[i] > th) { sgt += lv[i]; cgt += 1.f; }
    }
    float sb = 0.f;
    for (int i = lane; i < Kq; i += 32) {
        int idx = g_idx_bkg[b * Kq + i];
        sb += g_cas[(b * Tq + idx) * Cq + c];
    }
#pragma unroll
    for (int off = 16; off > 0; off >>= 1) {
        sgt += __shfl_xor_sync(0xffffffffu, sgt, off);
        cgt += __shfl_xor_sync(0xffffffffu, cgt, off);
        sb  += __shfl_xor_sync(0xffffffffu, sb,  off);
    }
    if (lane == 0) {
        g_sa[gw] = (sgt + ((float)Kq - cgt) * thf) / (float)Kq;
        g_sb[gw] = sb / (float)Kq;
    }
}

// ---------------------------------------------------------------------------
// K5: softmax over C for score_act / score_bkg (one warp per batch).
// ---------------------------------------------------------------------------
__global__ __launch_bounds__(32) void k_softmax_scores(float* __restrict__ out)
{
    const int b = blockIdx.x;
    const int lane = threadIdx.x;
    float va = (lane < Cq) ? g_sa[b * Cq + lane] : -INFINITY;
    float vb = (lane < Cq) ? g_sb[b * Cq + lane] : -INFINITY;
    float ma = va, mb = vb;
#pragma unroll
    for (int off = 16; off > 0; off >>= 1) {
        ma = fmaxf(ma, __shfl_xor_sync(0xffffffffu, ma, off));
        mb = fmaxf(mb, __shfl_xor_sync(0xffffffffu, mb, off));
    }
    float ea = (lane < Cq) ? expf(va - ma) : 0.f;
    float eb = (lane < Cq) ? expf(vb - mb) : 0.f;
    float sa = ea, sb = eb;
#pragma unroll
    for (int off = 16; off > 0; off >>= 1) {
        sa += __shfl_xor_sync(0xffffffffu, sa, off);
        sb += __shfl_xor_sync(0xffffffffu, sb, off);
    }
    if (lane < Cq) {
        out[OFF_SA + b * Cq + lane] = ea / sa;
        out[OFF_SB + b * Cq + lane] = eb / sb;
    }
}

// ---------------------------------------------------------------------------
extern "C" void kernel_launch(void* const* d_in, const int* in_sizes, int n_in,
                              void* d_out, int out_size)
{
    const float* x   = (const float*)d_in[0];   // (B,T,F)
    const float* W   = (const float*)d_in[1];   // (C,F)
    const float* mk  = (const float*)d_in[2];   // (B,T,F)
    const float* sel = (const float*)d_in[3];   // (B,T)
    float* out = (float*)d_out;

    static cudaStream_t s2 = nullptr;
    static cudaEvent_t evFork = nullptr, evJoin = nullptr;
    if (s2 == nullptr) {
        cudaStreamCreateWithFlags(&s2, cudaStreamNonBlocking);
        cudaEventCreateWithFlags(&evFork, cudaEventDisableTiming);
        cudaEventCreateWithFlags(&evJoin, cudaEventDisableTiming);
    }

    k_main<<<NROWS / ROWS_PER_BLOCK, 256>>>((const float4*)x, (const float4*)mk,
                                            (const float4*)W, out);
    k_select<<<Bq, 256>>>(sel);

    // fork: gather runs concurrently with scores+softmax
    cudaEventRecord(evFork, (cudaStream_t)0);
    cudaStreamWaitEvent(s2, evFork, 0);
    {
        dim3 grid(Bq * Kq, 2);
        k_gather<<<grid, 128, 0, s2>>>((const float4*)x, out);
    }
    k_scores<<<(Bq * Cq + 7) / 8, 256>>>();
    k_softmax_scores<<<Bq, 32>>>(out);
    cudaEventRecord(evJoin, s2);
    cudaStreamWaitEvent((cudaStream_t)0, evJoin, 0);
}